// round 2
// baseline (speedup 1.0000x reference)
#include <cuda_runtime.h>
#include <cstdint>
#include <cstddef>

#define BSZ 32
#define TSZ 2048
#define DSZ 512
#define NSZ 512

// ---------------- device scratch (allocation-free: __device__ globals) -------
__device__ float4 g_Upk[DSZ * NSZ];                      // [k][n] -> (Ui,Uf,Ug,Uc)   4 MB
__device__ float  g_G[(size_t)TSZ * BSZ * 4 * NSZ];      // [t][b][g*512+n]         512 MB
__device__ float  g_hs[(size_t)TSZ * BSZ * NSZ];         // [t][b][n]               128 MB
__device__ int    g_count;
__device__ int    g_flag;

// ---------------- small prep kernels ----------------------------------------
__global__ void pack_u_kernel(const float* __restrict__ Ui, const float* __restrict__ Uf,
                              const float* __restrict__ Ug, const float* __restrict__ Uc)
{
    int i = blockIdx.x * 256 + threadIdx.x;     // 0 .. 512*512-1
    g_Upk[i] = make_float4(Ui[i], Uf[i], Ug[i], Uc[i]);
}

__global__ void reset_sync_kernel()
{
    g_count = 0;
    g_flag  = 0;
}

// ---------------- SGEMM: input projections (4 gates via blockIdx.z) ----------
// C[(t*32+b)*2048 + z*512 + n] = x[(b,t),:] @ W_z[:,n] + bias_z[n]
__global__ __launch_bounds__(256) void gemm_gates_kernel(
    const float* __restrict__ x,
    const float* __restrict__ W0, const float* __restrict__ W1,
    const float* __restrict__ W2, const float* __restrict__ W3,
    const float* __restrict__ b0, const float* __restrict__ b1,
    const float* __restrict__ b2, const float* __restrict__ b3)
{
    __shared__ __align__(16) float As[16][132];
    __shared__ __align__(16) float Bs[16][128];

    const int z = blockIdx.z;
    const float* W    = (z == 0) ? W0 : (z == 1) ? W1 : (z == 2) ? W2 : W3;
    const float* bias = (z == 0) ? b0 : (z == 1) ? b1 : (z == 2) ? b2 : b3;

    const int tid   = threadIdx.x;
    const int ty    = tid >> 4;          // 0..15
    const int tx    = tid & 15;          // 0..15
    const int mbase = blockIdx.y * 128;
    const int nbase = blockIdx.x * 128;  // within gate (N=512 -> 4 tiles)

    const int am = tid >> 2;             // 0..63
    const int ak = (tid & 3) * 4;        // 0,4,8,12
    const int bk = tid >> 5;             // 0..7
    const int bn = (tid & 31) * 4;       // 0..124

    float acc[8][8];
#pragma unroll
    for (int i = 0; i < 8; i++)
#pragma unroll
        for (int jj = 0; jj < 8; jj++) acc[i][jj] = 0.f;

    for (int kt = 0; kt < DSZ; kt += 16) {
        float4 a0 = *(const float4*)&x[(size_t)(mbase + am)      * DSZ + kt + ak];
        float4 a1 = *(const float4*)&x[(size_t)(mbase + am + 64) * DSZ + kt + ak];
        float4 w0 = *(const float4*)&W[(size_t)(kt + bk)     * NSZ + nbase + bn];
        float4 w1 = *(const float4*)&W[(size_t)(kt + bk + 8) * NSZ + nbase + bn];
        __syncthreads();
        As[ak + 0][am] = a0.x; As[ak + 1][am] = a0.y; As[ak + 2][am] = a0.z; As[ak + 3][am] = a0.w;
        As[ak + 0][am + 64] = a1.x; As[ak + 1][am + 64] = a1.y; As[ak + 2][am + 64] = a1.z; As[ak + 3][am + 64] = a1.w;
        *(float4*)&Bs[bk][bn]     = w0;
        *(float4*)&Bs[bk + 8][bn] = w1;
        __syncthreads();
#pragma unroll
        for (int k = 0; k < 16; k++) {
            float a_[8], b_[8];
            *(float4*)&a_[0] = *(const float4*)&As[k][ty * 8];
            *(float4*)&a_[4] = *(const float4*)&As[k][ty * 8 + 4];
            *(float4*)&b_[0] = *(const float4*)&Bs[k][tx * 8];
            *(float4*)&b_[4] = *(const float4*)&Bs[k][tx * 8 + 4];
#pragma unroll
            for (int i = 0; i < 8; i++)
#pragma unroll
                for (int jj = 0; jj < 8; jj++)
                    acc[i][jj] = fmaf(a_[i], b_[jj], acc[i][jj]);
        }
    }

    float bv[8];
#pragma unroll
    for (int jj = 0; jj < 8; jj++) bv[jj] = bias[nbase + tx * 8 + jj];

#pragma unroll
    for (int i = 0; i < 8; i++) {
        int r  = mbase + ty * 8 + i;     // r = b*2048 + t
        int tt = r & (TSZ - 1);
        int bb = r >> 11;
        size_t off = ((size_t)tt * BSZ + bb) * (4 * NSZ) + (size_t)z * NSZ + nbase + tx * 8;
        float4 v0 = make_float4(acc[i][0] + bv[0], acc[i][1] + bv[1], acc[i][2] + bv[2], acc[i][3] + bv[3]);
        float4 v1 = make_float4(acc[i][4] + bv[4], acc[i][5] + bv[5], acc[i][6] + bv[6], acc[i][7] + bv[7]);
        *(float4*)&g_G[off]     = v0;
        *(float4*)&g_G[off + 4] = v1;
    }
}

// ---------------- SGEMM: output projection + ReLU ----------------------------
// out[(b*2048+t)*512+m] = relu(hs[(t*32+b),:] @ Wo[:,m] + bo[m])
__global__ __launch_bounds__(256) void gemm_out_kernel(
    const float* __restrict__ Wo, const float* __restrict__ bo, float* __restrict__ out)
{
    __shared__ __align__(16) float As[16][132];
    __shared__ __align__(16) float Bs[16][128];

    const float* A = g_hs;

    const int tid   = threadIdx.x;
    const int ty    = tid >> 4;
    const int tx    = tid & 15;
    const int mbase = blockIdx.y * 128;
    const int nbase = blockIdx.x * 128;

    const int am = tid >> 2;
    const int ak = (tid & 3) * 4;
    const int bk = tid >> 5;
    const int bn = (tid & 31) * 4;

    float acc[8][8];
#pragma unroll
    for (int i = 0; i < 8; i++)
#pragma unroll
        for (int jj = 0; jj < 8; jj++) acc[i][jj] = 0.f;

    for (int kt = 0; kt < NSZ; kt += 16) {
        float4 a0 = *(const float4*)&A[(size_t)(mbase + am)      * NSZ + kt + ak];
        float4 a1 = *(const float4*)&A[(size_t)(mbase + am + 64) * NSZ + kt + ak];
        float4 w0 = *(const float4*)&Wo[(size_t)(kt + bk)     * NSZ + nbase + bn];
        float4 w1 = *(const float4*)&Wo[(size_t)(kt + bk + 8) * NSZ + nbase + bn];
        __syncthreads();
        As[ak + 0][am] = a0.x; As[ak + 1][am] = a0.y; As[ak + 2][am] = a0.z; As[ak + 3][am] = a0.w;
        As[ak + 0][am + 64] = a1.x; As[ak + 1][am + 64] = a1.y; As[ak + 2][am + 64] = a1.z; As[ak + 3][am + 64] = a1.w;
        *(float4*)&Bs[bk][bn]     = w0;
        *(float4*)&Bs[bk + 8][bn] = w1;
        __syncthreads();
#pragma unroll
        for (int k = 0; k < 16; k++) {
            float a_[8], b_[8];
            *(float4*)&a_[0] = *(const float4*)&As[k][ty * 8];
            *(float4*)&a_[4] = *(const float4*)&As[k][ty * 8 + 4];
            *(float4*)&b_[0] = *(const float4*)&Bs[k][tx * 8];
            *(float4*)&b_[4] = *(const float4*)&Bs[k][tx * 8 + 4];
#pragma unroll
            for (int i = 0; i < 8; i++)
#pragma unroll
                for (int jj = 0; jj < 8; jj++)
                    acc[i][jj] = fmaf(a_[i], b_[jj], acc[i][jj]);
        }
    }

    float bv[8];
#pragma unroll
    for (int jj = 0; jj < 8; jj++) bv[jj] = bo[nbase + tx * 8 + jj];

#pragma unroll
    for (int i = 0; i < 8; i++) {
        int r  = mbase + ty * 8 + i;     // r = t*32 + b
        int tt = r >> 5;
        int bb = r & 31;
        size_t off = ((size_t)bb * TSZ + tt) * NSZ + nbase + tx * 8;
        float4 v0 = make_float4(fmaxf(acc[i][0] + bv[0], 0.f), fmaxf(acc[i][1] + bv[1], 0.f),
                                fmaxf(acc[i][2] + bv[2], 0.f), fmaxf(acc[i][3] + bv[3], 0.f));
        float4 v1 = make_float4(fmaxf(acc[i][4] + bv[4], 0.f), fmaxf(acc[i][5] + bv[5], 0.f),
                                fmaxf(acc[i][6] + bv[6], 0.f), fmaxf(acc[i][7] + bv[7], 0.f));
        *(float4*)&out[off]     = v0;
        *(float4*)&out[off + 4] = v1;
    }
}

// ---------------- persistent recurrence kernel -------------------------------
// grid = 128 CTAs (all co-resident on 148 SMs), 512 threads each.
// CTA (cg, bh): cg = blockIdx.x>>1 owns n-columns [cg*8, cg*8+8);
//               bh = blockIdx.x&1 owns batches [bh*16, bh*16+16).
// warp w: kc = w&3 -> k-chunk of 128; bq = w>>2 -> 4 of the CTA's 16 batches.
// lane: bsub = lane>>3 (batch within quad), j = lane&7 (column).
// smem: U slice [512][8] float4 (64KB) + h [16][516] (33KB) + partials (8KB) + c (0.5KB)
#define HSTRIDE 516
#define SMEM_FLOATS (16384 + 16 * HSTRIDE + 4 * 128 * 4 + 128)

__global__ __launch_bounds__(512, 1) void lstm_recur_kernel()
{
    extern __shared__ float sm[];
    float4* U_s  = (float4*)sm;                          // [k*8 + j]
    float*  h_s  = sm + 16384;                           // [b][HSTRIDE]
    float4* part = (float4*)(sm + 16384 + 16 * HSTRIDE); // [kc*128 + out]
    float*  c_s  = sm + 16384 + 16 * HSTRIDE + 4 * 128 * 4;

    const int tid  = threadIdx.x;
    const int cg   = blockIdx.x >> 1;
    const int bh   = blockIdx.x & 1;
    const int lane = tid & 31;
    const int w    = tid >> 5;
    const int kc   = w & 3;
    const int bq   = w >> 2;
    const int bsub = lane >> 3;
    const int j    = lane & 7;
    const int bloc = bq * 4 + bsub;
    const int k0   = kc * 128;

    // one-time: load this CTA's U slice (all k, its 8 columns, 4 gates packed)
    for (int i = tid; i < 4096; i += 512) {
        int k = i >> 3, jj = i & 7;
        U_s[i] = g_Upk[k * NSZ + cg * 8 + jj];
    }
    if (tid < 128) c_s[tid] = 0.f;

    for (int t = 0; t < TSZ; t++) {
        // stage h_{t-1} for this CTA's 16 batches into smem
        if (t == 0) {
            for (int i = tid; i < 2048; i += 512) {
                int b = i >> 7, k4 = (i & 127) << 2;
                *(float4*)&h_s[b * HSTRIDE + k4] = make_float4(0.f, 0.f, 0.f, 0.f);
            }
        } else {
            const float* hp = &g_hs[((size_t)(t - 1) * BSZ + bh * 16) * NSZ];
            for (int i = tid; i < 2048; i += 512) {
                int b = i >> 7, k4 = (i & 127) << 2;
                *(float4*)&h_s[b * HSTRIDE + k4] = *(const float4*)&hp[b * NSZ + k4];
            }
        }
        __syncthreads();

        // partial h @ U over this warp's 128-k chunk, 4 gates at once
        float4 acc = make_float4(0.f, 0.f, 0.f, 0.f);
        const float*  hrow = &h_s[bloc * HSTRIDE + k0];
        const float4* up   = &U_s[k0 * 8 + j];
#pragma unroll 8
        for (int kk = 0; kk < 128; kk += 4) {
            float4 hv = *(const float4*)&hrow[kk];
            float4 u0 = up[(kk + 0) * 8];
            float4 u1 = up[(kk + 1) * 8];
            float4 u2 = up[(kk + 2) * 8];
            float4 u3 = up[(kk + 3) * 8];
            acc.x = fmaf(hv.x, u0.x, acc.x); acc.y = fmaf(hv.x, u0.y, acc.y);
            acc.z = fmaf(hv.x, u0.z, acc.z); acc.w = fmaf(hv.x, u0.w, acc.w);
            acc.x = fmaf(hv.y, u1.x, acc.x); acc.y = fmaf(hv.y, u1.y, acc.y);
            acc.z = fmaf(hv.y, u1.z, acc.z); acc.w = fmaf(hv.y, u1.w, acc.w);
            acc.x = fmaf(hv.z, u2.x, acc.x); acc.y = fmaf(hv.z, u2.y, acc.y);
            acc.z = fmaf(hv.z, u2.z, acc.z); acc.w = fmaf(hv.z, u2.w, acc.w);
            acc.x = fmaf(hv.w, u3.x, acc.x); acc.y = fmaf(hv.w, u3.y, acc.y);
            acc.z = fmaf(hv.w, u3.z, acc.z); acc.w = fmaf(hv.w, u3.w, acc.w);
        }
        part[kc * 128 + bloc * 8 + j] = acc;
        __syncthreads();

        // reduce split-k, apply gates, update c, emit h_t
        if (tid < 128) {
            int b  = tid >> 3, jj = tid & 7;
            float4 s  = part[tid];
            float4 p1 = part[128 + tid];
            float4 p2 = part[256 + tid];
            float4 p3 = part[384 + tid];
            s.x += p1.x + p2.x + p3.x;
            s.y += p1.y + p2.y + p3.y;
            s.z += p1.z + p2.z + p3.z;
            s.w += p1.w + p2.w + p3.w;

            int bg = bh * 16 + b;
            int n  = cg * 8 + jj;
            size_t gbase = ((size_t)t * BSZ + bg) * (4 * NSZ) + n;
            float xi = g_G[gbase];
            float xf = g_G[gbase + NSZ];
            float xg = g_G[gbase + 2 * NSZ];
            float xc = g_G[gbase + 3 * NSZ];

            float ig = 1.f / (1.f + __expf(-(s.x + xi)));
            float fg = 1.f / (1.f + __expf(-(s.y + xf)));
            float gg = 1.f / (1.f + __expf(-(s.z + xg)));
            float ct = tanhf(s.w + xc);

            float c = fg * c_s[tid] + ig * ct;
            c_s[tid] = c;
            float h = gg * tanhf(c);
            g_hs[((size_t)t * BSZ + bg) * NSZ + n] = h;
            __threadfence();
        }

        // grid-wide barrier (all 128 CTAs co-resident)
        __syncthreads();
        if (tid == 0) {
            int v = atomicAdd(&g_count, 1);
            if (v == (int)gridDim.x - 1) {
                g_count = 0;
                __threadfence();
                atomicExch(&g_flag, t + 1);
            } else {
                while (((volatile int*)&g_flag)[0] < t + 1) {}
                __threadfence();
            }
        }
        __syncthreads();
    }
}

// ---------------- launcher ---------------------------------------------------
extern "C" void kernel_launch(void* const* d_in, const int* in_sizes, int n_in,
                              void* d_out, int out_size)
{
    (void)in_sizes; (void)n_in; (void)out_size;
    const float* x   = (const float*)d_in[0];
    const float* W_i = (const float*)d_in[1];
    const float* U_i = (const float*)d_in[2];
    const float* W_f = (const float*)d_in[3];
    const float* U_f = (const float*)d_in[4];
    const float* W_g = (const float*)d_in[5];
    const float* U_g = (const float*)d_in[6];
    const float* W_c = (const float*)d_in[7];
    const float* U_c = (const float*)d_in[8];
    const float* W_o = (const float*)d_in[9];
    const float* b_i = (const float*)d_in[10];
    const float* b_f = (const float*)d_in[11];
    const float* b_g = (const float*)d_in[12];
    const float* b_c = (const float*)d_in[13];
    const float* b_o = (const float*)d_in[14];
    float* out = (float*)d_out;

    cudaFuncSetAttribute(lstm_recur_kernel,
                         cudaFuncAttributeMaxDynamicSharedMemorySize,
                         SMEM_FLOATS * 4);

    // 1) pack U gates as float4 per (k,n)
    pack_u_kernel<<<(DSZ * NSZ) / 256, 256>>>(U_i, U_f, U_g, U_c);

    // 2) input projections for all gates (bias folded in)
    {
        dim3 grid(NSZ / 128, (BSZ * TSZ) / 128, 4);
        gemm_gates_kernel<<<grid, 256>>>(x, W_i, W_f, W_g, W_c, b_i, b_f, b_g, b_c);
    }

    // 3) reset grid-barrier state, then persistent recurrence
    reset_sync_kernel<<<1, 1>>>();
    lstm_recur_kernel<<<128, 512, SMEM_FLOATS * 4>>>();

    // 4) output projection + ReLU
    {
        dim3 grid(NSZ / 128, (BSZ * TSZ) / 128, 1);
        gemm_out_kernel<<<grid, 256>>>(W_o, b_o, out);
    }
}

// round 5
// speedup vs baseline: 1.1566x; 1.1566x over previous
#include <cuda_runtime.h>
#include <cuda_bf16.h>
#include <cstdint>
#include <cstddef>

#define BSZ 32
#define TSZ 2048
#define DSZ 512
#define NSZ 512
#define MROWS (BSZ * TSZ)      // 65536
#define NCAT  (4 * NSZ)        // 2048

// ---------------- device scratch (allocation-free: __device__ globals) -------
__device__ float4 g_Upk[DSZ * NSZ];                      // 4 MB
__device__ float  g_G[(size_t)TSZ * BSZ * NCAT];         // 512 MB  [t][b][gate*512+n]
__device__ float  g_hs[(size_t)TSZ * BSZ * NSZ];         // 128 MB  [t][b][n]
__device__ __nv_bfloat16 g_Ahi[(size_t)MROWS * DSZ];     // 64 MB
__device__ __nv_bfloat16 g_Alo[(size_t)MROWS * DSZ];     // 64 MB
__device__ __nv_bfloat16 g_Bhi[(size_t)NCAT * DSZ];      // 2 MB   [n][k] (W^T)
__device__ __nv_bfloat16 g_Blo[(size_t)NCAT * DSZ];      // 2 MB
__device__ float  g_biascat[NCAT];
__device__ int    g_count;
__device__ int    g_flag;

// ---------------- PTX helpers (baseline PTX only: sm_80+ features) ----------
__device__ __forceinline__ uint32_t smem_to_u32(const void* p) {
    uint32_t a;
    asm("{ .reg .u64 t; cvta.to.shared.u64 t, %1; cvt.u32.u64 %0, t; }" : "=r"(a) : "l"(p));
    return a;
}
#define CP_ASYNC16(dst, src) \
    asm volatile("cp.async.cg.shared.global [%0], [%1], 16;" :: "r"(dst), "l"(src))
#define CP_COMMIT() asm volatile("cp.async.commit_group;" ::: "memory")
#define CP_WAIT(n)  asm volatile("cp.async.wait_group %0;" :: "n"(n) : "memory")

__device__ __forceinline__ void ldsm_x4(uint32_t* r, uint32_t addr) {
    asm volatile("ldmatrix.sync.aligned.m8n8.x4.shared.b16 {%0,%1,%2,%3}, [%4];"
                 : "=r"(r[0]), "=r"(r[1]), "=r"(r[2]), "=r"(r[3]) : "r"(addr));
}
__device__ __forceinline__ void ldsm_x2(uint32_t* r, uint32_t addr) {
    asm volatile("ldmatrix.sync.aligned.m8n8.x2.shared.b16 {%0,%1}, [%2];"
                 : "=r"(r[0]), "=r"(r[1]) : "r"(addr));
}
__device__ __forceinline__ void mma16816(float* c, const uint32_t* a, const uint32_t* b) {
    asm volatile("mma.sync.aligned.m16n8k16.row.col.f32.bf16.bf16.f32 "
                 "{%0,%1,%2,%3}, {%4,%5,%6,%7}, {%8,%9}, {%0,%1,%2,%3};"
                 : "+f"(c[0]), "+f"(c[1]), "+f"(c[2]), "+f"(c[3])
                 : "r"(a[0]), "r"(a[1]), "r"(a[2]), "r"(a[3]), "r"(b[0]), "r"(b[1]));
}

// ---------------- small prep kernels ----------------------------------------
__global__ void pack_u_kernel(const float* __restrict__ Ui, const float* __restrict__ Uf,
                              const float* __restrict__ Ug, const float* __restrict__ Uc)
{
    int i = blockIdx.x * 256 + threadIdx.x;
    g_Upk[i] = make_float4(Ui[i], Uf[i], Ug[i], Uc[i]);
}

__global__ void reset_sync_kernel() { g_count = 0; g_flag = 0; }

__device__ __forceinline__ unsigned bf16pack2(float a, float b)
{
    return (unsigned)__bfloat16_as_ushort(__float2bfloat16(a)) |
           ((unsigned)__bfloat16_as_ushort(__float2bfloat16(b)) << 16);
}
__device__ __forceinline__ float bf16res(float a)
{
    return a - __bfloat162float(__float2bfloat16(a));
}

__global__ void cvt_x_kernel(const float* __restrict__ src)
{
    size_t i = (size_t)blockIdx.x * 256 + threadIdx.x;
    float4 v = ((const float4*)src)[i];
    uint2 ph, pl;
    ph.x = bf16pack2(v.x, v.y);
    ph.y = bf16pack2(v.z, v.w);
    pl.x = bf16pack2(bf16res(v.x), bf16res(v.y));
    pl.y = bf16pack2(bf16res(v.z), bf16res(v.w));
    ((uint2*)g_Ahi)[i] = ph;
    ((uint2*)g_Alo)[i] = pl;
}

__global__ void cvt_hs_kernel()
{
    size_t i = (size_t)blockIdx.x * 256 + threadIdx.x;
    float4 v = ((const float4*)g_hs)[i];
    uint2 ph, pl;
    ph.x = bf16pack2(v.x, v.y);
    ph.y = bf16pack2(v.z, v.w);
    pl.x = bf16pack2(bf16res(v.x), bf16res(v.y));
    pl.y = bf16pack2(bf16res(v.z), bf16res(v.w));
    ((uint2*)g_Ahi)[i] = ph;
    ((uint2*)g_Alo)[i] = pl;
}

// W [512 k][512 n] -> g_Bhi/g_Blo rows (rowbase+n), cols k (transposed, hi/lo)
__global__ void wtrans_kernel(const float* __restrict__ W, int rowbase)
{
    __shared__ float t[32][33];
    int tx = threadIdx.x, ty = threadIdx.y;              // 32 x 8
    int n0 = blockIdx.x * 32, k0 = blockIdx.y * 32;
#pragma unroll
    for (int r = 0; r < 32; r += 8)
        t[ty + r][tx] = W[(size_t)(k0 + ty + r) * NSZ + n0 + tx];
    __syncthreads();
#pragma unroll
    for (int r = 0; r < 32; r += 8) {
        float v = t[tx][ty + r];
        size_t o = (size_t)(rowbase + n0 + ty + r) * DSZ + k0 + tx;
        g_Bhi[o] = __float2bfloat16(v);
        g_Blo[o] = __float2bfloat16(bf16res(v));
    }
}

__global__ void biascat_kernel(const float* __restrict__ bi, const float* __restrict__ bf,
                               const float* __restrict__ bg, const float* __restrict__ bc)
{
    int i = blockIdx.x * 256 + threadIdx.x;
    if (i < NSZ) {
        g_biascat[i]           = bi[i];
        g_biascat[NSZ + i]     = bf[i];
        g_biascat[2 * NSZ + i] = bg[i];
        g_biascat[3 * NSZ + i] = bc[i];
    }
}

// ---------------- HMMA GEMM (mma.sync bf16 hi/lo, fp32 accum) ----------------
// C[M=65536, ncols] = (Ahi+Alo)[M,512] @ (Bhi+Blo)^T[ncols,512] + bias
// mode 0: C=g_G, A row r=b*2048+t -> g_G[(t*32+b)*2048 + n]
// mode 1: C=out, A row r=t*32+b  -> out[(b*2048+t)*512 + n], ReLU
// 128x128 tile, 8 warps (2m x 4n), warp tile 64x32, K-chunk 64, double buffer.
#define GSM_TOTAL (2 * 65536)

__global__ __launch_bounds__(256, 1) void gemm_mma_kernel(
    const float* __restrict__ bias_ext, float* __restrict__ out_ext, int mode)
{
    extern __shared__ char smem[];
    const uint32_t smem_base = smem_to_u32(smem);
    const int tid  = threadIdx.x;
    const int wid  = tid >> 5;
    const int lane = tid & 31;
    const int wm   = wid & 1;       // 2 m-warps
    const int wn   = wid >> 1;      // 4 n-warps
    const int mbase = blockIdx.y * 128;
    const int nbase = blockIdx.x * 128;

    // cp.async destination offsets (swizzled SW128, 16B granules)
    uint32_t dsts[16];
#pragma unroll
    for (int v = 0; v < 16; v++) {
        int row = (v & 3) * 32 + (tid >> 3);
        uint32_t off = row * 128 + (tid & 7) * 16;
        dsts[v] = (uint32_t)((v >> 2) * 16384) + (off ^ ((off >> 3) & 0x70));
    }

#define ISSUE_CHUNK(KT, BUFOFF) do {                                                 \
    int _kt = (KT);                                                                  \
    uint32_t _bo = (BUFOFF);                                                         \
    _Pragma("unroll")                                                                \
    for (int v = 0; v < 16; v++) {                                                   \
        const __nv_bfloat16* bp = (v < 4) ? g_Ahi : (v < 8) ? g_Alo                  \
                                  : (v < 12) ? g_Bhi : g_Blo;                        \
        int rb = (v < 8) ? mbase : nbase;                                            \
        int row = (v & 3) * 32 + (tid >> 3);                                         \
        CP_ASYNC16(smem_base + _bo + dsts[v],                                        \
                   bp + ((size_t)(rb + row) << 9) + _kt + ((tid & 7) << 3));         \
    }                                                                                \
    CP_COMMIT();                                                                     \
} while (0)

    // fragment address precomputes
    uint32_t a_rowoff[4], a_swz[4];
#pragma unroll
    for (int mf = 0; mf < 4; mf++) {
        int row = wm * 64 + mf * 16 + (lane & 15);
        a_rowoff[mf] = row * 128;
        a_swz[mf]    = (row & 7) << 4;
    }
    const uint32_t a_cb = (uint32_t)(lane >> 4) * 16;
    uint32_t b_rowoff[4], b_swz[4];
#pragma unroll
    for (int nf = 0; nf < 4; nf++) {
        int row = wn * 32 + nf * 8 + (lane & 7);
        b_rowoff[nf] = row * 128;
        b_swz[nf]    = (row & 7) << 4;
    }
    const uint32_t b_cb = (uint32_t)((lane >> 3) & 1) * 16;

    float acc[4][4][4];
#pragma unroll
    for (int mf = 0; mf < 4; mf++)
#pragma unroll
        for (int nf = 0; nf < 4; nf++)
#pragma unroll
            for (int q = 0; q < 4; q++) acc[mf][nf][q] = 0.f;

    ISSUE_CHUNK(0, 0);

    for (int i = 0; i < 8; i++) {
        if (i < 7) {
            ISSUE_CHUNK((i + 1) * 64, (uint32_t)(((i + 1) & 1) * 65536));
            CP_WAIT(1);
        } else {
            CP_WAIT(0);
        }
        __syncthreads();

        const uint32_t base = smem_base + (uint32_t)((i & 1) * 65536);
#pragma unroll
        for (int k16 = 0; k16 < 4; k16++) {
            const uint32_t kb = (uint32_t)(k16 * 32);
            uint32_t aH[4][4], aL[4][4], bH[4][2], bL[4][2];
#pragma unroll
            for (int mf = 0; mf < 4; mf++) {
                uint32_t co = (kb + a_cb) ^ a_swz[mf];
                ldsm_x4(aH[mf], base + a_rowoff[mf] + co);
                ldsm_x4(aL[mf], base + 16384 + a_rowoff[mf] + co);
            }
#pragma unroll
            for (int nf = 0; nf < 4; nf++) {
                uint32_t co = (kb + b_cb) ^ b_swz[nf];
                ldsm_x2(bH[nf], base + 32768 + b_rowoff[nf] + co);
                ldsm_x2(bL[nf], base + 49152 + b_rowoff[nf] + co);
            }
#pragma unroll
            for (int mf = 0; mf < 4; mf++)
#pragma unroll
                for (int nf = 0; nf < 4; nf++) {
                    mma16816(acc[mf][nf], aH[mf], bH[nf]);
                    mma16816(acc[mf][nf], aH[mf], bL[nf]);
                    mma16816(acc[mf][nf], aL[mf], bH[nf]);
                }
        }
        __syncthreads();
    }

    // epilogue: direct fp32 stores with bias (+ReLU for mode 1)
    const float* bias = mode ? bias_ext : g_biascat;
    float* C = mode ? out_ext : g_G;
    const int ncols = mode ? NSZ : NCAT;

#pragma unroll
    for (int mf = 0; mf < 4; mf++) {
#pragma unroll
        for (int h = 0; h < 2; h++) {
            int r = mbase + wm * 64 + mf * 16 + (lane >> 2) + h * 8;
            size_t crow;
            if (mode == 0) {
                int tt = r & (TSZ - 1), bb = r >> 11;
                crow = ((size_t)tt * BSZ + bb) * (size_t)ncols;
            } else {
                int tt = r >> 5, bb = r & 31;
                crow = ((size_t)bb * TSZ + tt) * (size_t)ncols;
            }
#pragma unroll
            for (int nf = 0; nf < 4; nf++) {
                int col = nbase + wn * 32 + nf * 8 + (lane & 3) * 2;
                float2 bv = *(const float2*)&bias[col];
                float2 o;
                o.x = acc[mf][nf][h * 2 + 0] + bv.x;
                o.y = acc[mf][nf][h * 2 + 1] + bv.y;
                if (mode) { o.x = fmaxf(o.x, 0.f); o.y = fmaxf(o.y, 0.f); }
                *(float2*)&C[crow + col] = o;
            }
        }
    }
#undef ISSUE_CHUNK
}

// ---------------- persistent recurrence kernel (unchanged from R2) ----------
#define HSTRIDE 516
#define SMEM_FLOATS (16384 + 16 * HSTRIDE + 4 * 128 * 4 + 128)

__global__ __launch_bounds__(512, 1) void lstm_recur_kernel()
{
    extern __shared__ float sm[];
    float4* U_s  = (float4*)sm;
    float*  h_s  = sm + 16384;
    float4* part = (float4*)(sm + 16384 + 16 * HSTRIDE);
    float*  c_s  = sm + 16384 + 16 * HSTRIDE + 4 * 128 * 4;

    const int tid  = threadIdx.x;
    const int cg   = blockIdx.x >> 1;
    const int bh   = blockIdx.x & 1;
    const int lane = tid & 31;
    const int w    = tid >> 5;
    const int kc   = w & 3;
    const int bq   = w >> 2;
    const int bsub = lane >> 3;
    const int j    = lane & 7;
    const int bloc = bq * 4 + bsub;
    const int k0   = kc * 128;

    for (int i = tid; i < 4096; i += 512) {
        int k = i >> 3, jj = i & 7;
        U_s[i] = g_Upk[k * NSZ + cg * 8 + jj];
    }
    if (tid < 128) c_s[tid] = 0.f;

    for (int t = 0; t < TSZ; t++) {
        if (t == 0) {
            for (int i = tid; i < 2048; i += 512) {
                int b = i >> 7, k4 = (i & 127) << 2;
                *(float4*)&h_s[b * HSTRIDE + k4] = make_float4(0.f, 0.f, 0.f, 0.f);
            }
        } else {
            const float* hp = &g_hs[((size_t)(t - 1) * BSZ + bh * 16) * NSZ];
            for (int i = tid; i < 2048; i += 512) {
                int b = i >> 7, k4 = (i & 127) << 2;
                *(float4*)&h_s[b * HSTRIDE + k4] = *(const float4*)&hp[b * NSZ + k4];
            }
        }
        __syncthreads();

        float4 acc = make_float4(0.f, 0.f, 0.f, 0.f);
        const float*  hrow = &h_s[bloc * HSTRIDE + k0];
        const float4* up   = &U_s[k0 * 8 + j];
#pragma unroll 8
        for (int kk = 0; kk < 128; kk += 4) {
            float4 hv = *(const float4*)&hrow[kk];
            float4 u0 = up[(kk + 0) * 8];
            float4 u1 = up[(kk + 1) * 8];
            float4 u2 = up[(kk + 2) * 8];
            float4 u3 = up[(kk + 3) * 8];
            acc.x = fmaf(hv.x, u0.x, acc.x); acc.y = fmaf(hv.x, u0.y, acc.y);
            acc.z = fmaf(hv.x, u0.z, acc.z); acc.w = fmaf(hv.x, u0.w, acc.w);
            acc.x = fmaf(hv.y, u1.x, acc.x); acc.y = fmaf(hv.y, u1.y, acc.y);
            acc.z = fmaf(hv.y, u1.z, acc.z); acc.w = fmaf(hv.y, u1.w, acc.w);
            acc.x = fmaf(hv.z, u2.x, acc.x); acc.y = fmaf(hv.z, u2.y, acc.y);
            acc.z = fmaf(hv.z, u2.z, acc.z); acc.w = fmaf(hv.z, u2.w, acc.w);
            acc.x = fmaf(hv.w, u3.x, acc.x); acc.y = fmaf(hv.w, u3.y, acc.y);
            acc.z = fmaf(hv.w, u3.z, acc.z); acc.w = fmaf(hv.w, u3.w, acc.w);
        }
        part[kc * 128 + bloc * 8 + j] = acc;
        __syncthreads();

        if (tid < 128) {
            int b = tid >> 3, jj = tid & 7;
            float4 s  = part[tid];
            float4 p1 = part[128 + tid];
            float4 p2 = part[256 + tid];
            float4 p3 = part[384 + tid];
            s.x += p1.x + p2.x + p3.x;
            s.y += p1.y + p2.y + p3.y;
            s.z += p1.z + p2.z + p3.z;
            s.w += p1.w + p2.w + p3.w;

            int bg = bh * 16 + b;
            int n  = cg * 8 + jj;
            size_t gbase = ((size_t)t * BSZ + bg) * (size_t)NCAT + n;
            float xi = g_G[gbase];
            float xf = g_G[gbase + NSZ];
            float xg = g_G[gbase + 2 * NSZ];
            float xc = g_G[gbase + 3 * NSZ];

            float ig = 1.f / (1.f + __expf(-(s.x + xi)));
            float fg = 1.f / (1.f + __expf(-(s.y + xf)));
            float gg = 1.f / (1.f + __expf(-(s.z + xg)));
            float ct = tanhf(s.w + xc);

            float c = fg * c_s[tid] + ig * ct;
            c_s[tid] = c;
            float h = gg * tanhf(c);
            g_hs[((size_t)t * BSZ + bg) * NSZ + n] = h;
            __threadfence();
        }

        __syncthreads();
        if (tid == 0) {
            int v = atomicAdd(&g_count, 1);
            if (v == (int)gridDim.x - 1) {
                g_count = 0;
                __threadfence();
                atomicExch(&g_flag, t + 1);
            } else {
                while (((volatile int*)&g_flag)[0] < t + 1) {}
                __threadfence();
            }
        }
        __syncthreads();
    }
}

// ---------------- launcher ---------------------------------------------------
extern "C" void kernel_launch(void* const* d_in, const int* in_sizes, int n_in,
                              void* d_out, int out_size)
{
    (void)in_sizes; (void)n_in; (void)out_size;
    const float* x   = (const float*)d_in[0];
    const float* W_i = (const float*)d_in[1];
    const float* U_i = (const float*)d_in[2];
    const float* W_f = (const float*)d_in[3];
    const float* U_f = (const float*)d_in[4];
    const float* W_g = (const float*)d_in[5];
    const float* U_g = (const float*)d_in[6];
    const float* W_c = (const float*)d_in[7];
    const float* U_c = (const float*)d_in[8];
    const float* W_o = (const float*)d_in[9];
    const float* b_i = (const float*)d_in[10];
    const float* b_f = (const float*)d_in[11];
    const float* b_g = (const float*)d_in[12];
    const float* b_c = (const float*)d_in[13];
    const float* b_o = (const float*)d_in[14];
    float* out = (float*)d_out;

    cudaFuncSetAttribute(lstm_recur_kernel,
                         cudaFuncAttributeMaxDynamicSharedMemorySize, SMEM_FLOATS * 4);
    cudaFuncSetAttribute(gemm_mma_kernel,
                         cudaFuncAttributeMaxDynamicSharedMemorySize, GSM_TOTAL);

    // 1) prep: U pack, x->bf16 hi/lo, W^T->bf16 hi/lo, bias concat
    pack_u_kernel<<<(DSZ * NSZ) / 256, 256>>>(U_i, U_f, U_g, U_c);
    cvt_x_kernel<<<(int)(((size_t)MROWS * DSZ / 4) / 256), 256>>>(x);
    {
        dim3 g(16, 16), b(32, 8);
        wtrans_kernel<<<g, b>>>(W_i, 0);
        wtrans_kernel<<<g, b>>>(W_f, NSZ);
        wtrans_kernel<<<g, b>>>(W_g, 2 * NSZ);
        wtrans_kernel<<<g, b>>>(W_c, 3 * NSZ);
    }
    biascat_kernel<<<2, 256>>>(b_i, b_f, b_g, b_c);

    // 2) input projections for all 4 gates: HMMA GEMM -> g_G
    gemm_mma_kernel<<<dim3(NCAT / 128, MROWS / 128), 256, GSM_TOTAL>>>(nullptr, nullptr, 0);

    // 3) recurrence
    reset_sync_kernel<<<1, 1>>>();
    lstm_recur_kernel<<<128, 512, SMEM_FLOATS * 4>>>();

    // 4) output projection: hs->bf16, Wo^T->bf16, GEMM + ReLU -> out
    cvt_hs_kernel<<<(int)(((size_t)MROWS * NSZ / 4) / 256), 256>>>();
    {
        dim3 g(16, 16), b(32, 8);
        wtrans_kernel<<<g, b>>>(W_o, 0);
    }
    gemm_mma_kernel<<<dim3(NSZ / 128, MROWS / 128), 256, GSM_TOTAL>>>(b_o, out, 1);
}

// round 6
// speedup vs baseline: 1.2270x; 1.0608x over previous
#include <cuda_runtime.h>
#include <cuda_bf16.h>
#include <cstdint>
#include <cstddef>

#define BSZ 32
#define TSZ 2048
#define DSZ 512
#define NSZ 512
#define MROWS (BSZ * TSZ)      // 65536
#define NCAT  (4 * NSZ)        // 2048

// ---------------- device scratch (allocation-free: __device__ globals) -------
__device__ float4 g_Upk[DSZ * NSZ];                      // 4 MB
__device__ float  g_G[(size_t)TSZ * BSZ * NCAT];         // 512 MB  [t][b][gate*512+n]
__device__ float  g_hs[(size_t)TSZ * BSZ * NSZ];         // 128 MB  [t][b][n]
__device__ __nv_bfloat16 g_Ahi[(size_t)MROWS * DSZ];     // 64 MB
__device__ __nv_bfloat16 g_Alo[(size_t)MROWS * DSZ];     // 64 MB
__device__ __nv_bfloat16 g_Bhi[(size_t)NCAT * DSZ];      // 2 MB   [n][k] (W^T)
__device__ __nv_bfloat16 g_Blo[(size_t)NCAT * DSZ];      // 2 MB
__device__ float  g_biascat[NCAT];
__device__ int    g_cnt[8 * 32];                         // group counters (128B apart)
__device__ int    g_root2;
__device__ int    g_flagv;

// ---------------- PTX helpers (baseline PTX only: sm_80+/sm_100 family) -----
__device__ __forceinline__ uint32_t smem_to_u32(const void* p) {
    uint32_t a;
    asm("{ .reg .u64 t; cvta.to.shared.u64 t, %1; cvt.u32.u64 %0, t; }" : "=r"(a) : "l"(p));
    return a;
}
#define CP_ASYNC16(dst, src) \
    asm volatile("cp.async.cg.shared.global [%0], [%1], 16;" :: "r"(dst), "l"(src))
#define CP_COMMIT() asm volatile("cp.async.commit_group;" ::: "memory")
#define CP_WAIT(n)  asm volatile("cp.async.wait_group %0;" :: "n"(n) : "memory")

__device__ __forceinline__ void ldsm_x4(uint32_t* r, uint32_t addr) {
    asm volatile("ldmatrix.sync.aligned.m8n8.x4.shared.b16 {%0,%1,%2,%3}, [%4];"
                 : "=r"(r[0]), "=r"(r[1]), "=r"(r[2]), "=r"(r[3]) : "r"(addr));
}
__device__ __forceinline__ void ldsm_x2(uint32_t* r, uint32_t addr) {
    asm volatile("ldmatrix.sync.aligned.m8n8.x2.shared.b16 {%0,%1}, [%2];"
                 : "=r"(r[0]), "=r"(r[1]) : "r"(addr));
}
__device__ __forceinline__ void mma16816(float* c, const uint32_t* a, const uint32_t* b) {
    asm volatile("mma.sync.aligned.m16n8k16.row.col.f32.bf16.bf16.f32 "
                 "{%0,%1,%2,%3}, {%4,%5,%6,%7}, {%8,%9}, {%0,%1,%2,%3};"
                 : "+f"(c[0]), "+f"(c[1]), "+f"(c[2]), "+f"(c[3])
                 : "r"(a[0]), "r"(a[1]), "r"(a[2]), "r"(a[3]), "r"(b[0]), "r"(b[1]));
}

// packed fp32x2 FMA (Blackwell family, PTX ISA 8.6+, sm_100+)
#define FFMA2(acc, ab, uu) \
    asm("fma.rn.f32x2 %0, %1, %2, %0;" : "+l"(acc) : "l"(ab), "l"(uu))
#define PACK2SAME(dst, fv) \
    asm("mov.b64 %0, {%1, %1};" : "=l"(dst) : "r"(__float_as_uint(fv)))
#define UNPACK2(lo, hi, src) \
    asm("mov.b64 {%0, %1}, %2;" : "=r"(lo), "=r"(hi) : "l"(src))

// ---------------- small prep kernels ----------------------------------------
__global__ void pack_u_kernel(const float* __restrict__ Ui, const float* __restrict__ Uf,
                              const float* __restrict__ Ug, const float* __restrict__ Uc)
{
    int i = blockIdx.x * 256 + threadIdx.x;
    g_Upk[i] = make_float4(Ui[i], Uf[i], Ug[i], Uc[i]);
}

__global__ void reset_sync_kernel()
{
    int i = threadIdx.x;
    if (i < 256) g_cnt[i] = 0;
    if (i == 0) { g_root2 = 0; g_flagv = 0; }
}

__device__ __forceinline__ unsigned bf16pack2(float a, float b)
{
    return (unsigned)__bfloat16_as_ushort(__float2bfloat16(a)) |
           ((unsigned)__bfloat16_as_ushort(__float2bfloat16(b)) << 16);
}
__device__ __forceinline__ float bf16res(float a)
{
    return a - __bfloat162float(__float2bfloat16(a));
}

__global__ void cvt_x_kernel(const float* __restrict__ src)
{
    size_t i = (size_t)blockIdx.x * 256 + threadIdx.x;
    float4 v = ((const float4*)src)[i];
    uint2 ph, pl;
    ph.x = bf16pack2(v.x, v.y);
    ph.y = bf16pack2(v.z, v.w);
    pl.x = bf16pack2(bf16res(v.x), bf16res(v.y));
    pl.y = bf16pack2(bf16res(v.z), bf16res(v.w));
    ((uint2*)g_Ahi)[i] = ph;
    ((uint2*)g_Alo)[i] = pl;
}

__global__ void cvt_hs_kernel()
{
    size_t i = (size_t)blockIdx.x * 256 + threadIdx.x;
    float4 v = ((const float4*)g_hs)[i];
    uint2 ph, pl;
    ph.x = bf16pack2(v.x, v.y);
    ph.y = bf16pack2(v.z, v.w);
    pl.x = bf16pack2(bf16res(v.x), bf16res(v.y));
    pl.y = bf16pack2(bf16res(v.z), bf16res(v.w));
    ((uint2*)g_Ahi)[i] = ph;
    ((uint2*)g_Alo)[i] = pl;
}

// W [512 k][512 n] -> g_Bhi/g_Blo rows (rowbase+n), cols k (transposed, hi/lo)
__device__ __forceinline__ void wtrans_body(const float* __restrict__ W, int rowbase)
{
    __shared__ float t[32][33];
    int tx = threadIdx.x, ty = threadIdx.y;              // 32 x 8
    int n0 = blockIdx.x * 32, k0 = blockIdx.y * 32;
#pragma unroll
    for (int r = 0; r < 32; r += 8)
        t[ty + r][tx] = W[(size_t)(k0 + ty + r) * NSZ + n0 + tx];
    __syncthreads();
#pragma unroll
    for (int r = 0; r < 32; r += 8) {
        float v = t[tx][ty + r];
        size_t o = (size_t)(rowbase + n0 + ty + r) * DSZ + k0 + tx;
        g_Bhi[o] = __float2bfloat16(v);
        g_Blo[o] = __float2bfloat16(bf16res(v));
    }
}

__global__ void wtrans4_kernel(const float* __restrict__ W0, const float* __restrict__ W1,
                               const float* __restrict__ W2, const float* __restrict__ W3)
{
    int z = blockIdx.z;
    const float* W = (z == 0) ? W0 : (z == 1) ? W1 : (z == 2) ? W2 : W3;
    wtrans_body(W, z * NSZ);
}

__global__ void wtrans_kernel(const float* __restrict__ W, int rowbase)
{
    wtrans_body(W, rowbase);
}

__global__ void biascat_kernel(const float* __restrict__ bi, const float* __restrict__ bf,
                               const float* __restrict__ bg, const float* __restrict__ bc)
{
    int i = blockIdx.x * 256 + threadIdx.x;
    if (i < NSZ) {
        g_biascat[i]           = bi[i];
        g_biascat[NSZ + i]     = bf[i];
        g_biascat[2 * NSZ + i] = bg[i];
        g_biascat[3 * NSZ + i] = bc[i];
    }
}

// ---------------- HMMA GEMM (mma.sync bf16 hi/lo, fp32 accum) ----------------
#define GSM_TOTAL (2 * 65536)

__global__ __launch_bounds__(256, 1) void gemm_mma_kernel(
    const float* __restrict__ bias_ext, float* __restrict__ out_ext, int mode)
{
    extern __shared__ char smem[];
    const uint32_t smem_base = smem_to_u32(smem);
    const int tid  = threadIdx.x;
    const int wid  = tid >> 5;
    const int lane = tid & 31;
    const int wm   = wid & 1;
    const int wn   = wid >> 1;
    const int mbase = blockIdx.y * 128;
    const int nbase = blockIdx.x * 128;

    uint32_t dsts[16];
#pragma unroll
    for (int v = 0; v < 16; v++) {
        int row = (v & 3) * 32 + (tid >> 3);
        uint32_t off = row * 128 + (tid & 7) * 16;
        dsts[v] = (uint32_t)((v >> 2) * 16384) + (off ^ ((off >> 3) & 0x70));
    }

#define ISSUE_CHUNK(KT, BUFOFF) do {                                                 \
    int _kt = (KT);                                                                  \
    uint32_t _bo = (BUFOFF);                                                         \
    _Pragma("unroll")                                                                \
    for (int v = 0; v < 16; v++) {                                                   \
        const __nv_bfloat16* bp = (v < 4) ? g_Ahi : (v < 8) ? g_Alo                  \
                                  : (v < 12) ? g_Bhi : g_Blo;                        \
        int rb = (v < 8) ? mbase : nbase;                                            \
        int row = (v & 3) * 32 + (tid >> 3);                                         \
        CP_ASYNC16(smem_base + _bo + dsts[v],                                        \
                   bp + ((size_t)(rb + row) << 9) + _kt + ((tid & 7) << 3));         \
    }                                                                                \
    CP_COMMIT();                                                                     \
} while (0)

    uint32_t a_rowoff[4], a_swz[4];
#pragma unroll
    for (int mf = 0; mf < 4; mf++) {
        int row = wm * 64 + mf * 16 + (lane & 15);
        a_rowoff[mf] = row * 128;
        a_swz[mf]    = (row & 7) << 4;
    }
    const uint32_t a_cb = (uint32_t)(lane >> 4) * 16;
    uint32_t b_rowoff[4], b_swz[4];
#pragma unroll
    for (int nf = 0; nf < 4; nf++) {
        int row = wn * 32 + nf * 8 + (lane & 7);
        b_rowoff[nf] = row * 128;
        b_swz[nf]    = (row & 7) << 4;
    }
    const uint32_t b_cb = (uint32_t)((lane >> 3) & 1) * 16;

    float acc[4][4][4];
#pragma unroll
    for (int mf = 0; mf < 4; mf++)
#pragma unroll
        for (int nf = 0; nf < 4; nf++)
#pragma unroll
            for (int q = 0; q < 4; q++) acc[mf][nf][q] = 0.f;

    ISSUE_CHUNK(0, 0);

    for (int i = 0; i < 8; i++) {
        if (i < 7) {
            ISSUE_CHUNK((i + 1) * 64, (uint32_t)(((i + 1) & 1) * 65536));
            CP_WAIT(1);
        } else {
            CP_WAIT(0);
        }
        __syncthreads();

        const uint32_t base = smem_base + (uint32_t)((i & 1) * 65536);
#pragma unroll
        for (int k16 = 0; k16 < 4; k16++) {
            const uint32_t kb = (uint32_t)(k16 * 32);
            uint32_t aH[4][4], aL[4][4], bH[4][2], bL[4][2];
#pragma unroll
            for (int mf = 0; mf < 4; mf++) {
                uint32_t co = (kb + a_cb) ^ a_swz[mf];
                ldsm_x4(aH[mf], base + a_rowoff[mf] + co);
                ldsm_x4(aL[mf], base + 16384 + a_rowoff[mf] + co);
            }
#pragma unroll
            for (int nf = 0; nf < 4; nf++) {
                uint32_t co = (kb + b_cb) ^ b_swz[nf];
                ldsm_x2(bH[nf], base + 32768 + b_rowoff[nf] + co);
                ldsm_x2(bL[nf], base + 49152 + b_rowoff[nf] + co);
            }
#pragma unroll
            for (int mf = 0; mf < 4; mf++)
#pragma unroll
                for (int nf = 0; nf < 4; nf++) {
                    mma16816(acc[mf][nf], aH[mf], bH[nf]);
                    mma16816(acc[mf][nf], aH[mf], bL[nf]);
                    mma16816(acc[mf][nf], aL[mf], bH[nf]);
                }
        }
        __syncthreads();
    }

    const float* bias = mode ? bias_ext : g_biascat;
    float* C = mode ? out_ext : g_G;
    const int ncols = mode ? NSZ : NCAT;

#pragma unroll
    for (int mf = 0; mf < 4; mf++) {
#pragma unroll
        for (int h = 0; h < 2; h++) {
            int r = mbase + wm * 64 + mf * 16 + (lane >> 2) + h * 8;
            size_t crow;
            if (mode == 0) {
                int tt = r & (TSZ - 1), bb = r >> 11;
                crow = ((size_t)tt * BSZ + bb) * (size_t)ncols;
            } else {
                int tt = r >> 5, bb = r & 31;
                crow = ((size_t)bb * TSZ + tt) * (size_t)ncols;
            }
#pragma unroll
            for (int nf = 0; nf < 4; nf++) {
                int col = nbase + wn * 32 + nf * 8 + (lane & 3) * 2;
                float2 bv = *(const float2*)&bias[col];
                float2 o;
                o.x = acc[mf][nf][h * 2 + 0] + bv.x;
                o.y = acc[mf][nf][h * 2 + 1] + bv.y;
                if (mode) { o.x = fmaxf(o.x, 0.f); o.y = fmaxf(o.y, 0.f); }
                *(float2*)&C[crow + col] = o;
            }
        }
    }
#undef ISSUE_CHUNK
}

// ---------------- persistent recurrence kernel (f32x2 + 2-level barrier) ----
#define HSTRIDE 516
#define SMEM_FLOATS (16384 + 16 * HSTRIDE + 4 * 128 * 4 + 128)

__global__ __launch_bounds__(512, 1) void lstm_recur_kernel()
{
    extern __shared__ float sm[];
    float4* U_s  = (float4*)sm;                          // [k*8 + j] (Ui,Uf,Ug,Uc)
    float*  h_s  = sm + 16384;                           // [b][HSTRIDE]
    float4* part = (float4*)(sm + 16384 + 16 * HSTRIDE); // [kc*128 + bloc*8 + j]
    float*  c_s  = sm + 16384 + 16 * HSTRIDE + 4 * 128 * 4;

    const int tid  = threadIdx.x;
    const int bid  = blockIdx.x;
    const int cg   = bid >> 1;
    const int bh   = bid & 1;
    const int lane = tid & 31;
    const int w    = tid >> 5;
    const int kc   = w & 3;
    const int bq   = w >> 2;
    const int bsub = lane >> 3;
    const int j    = lane & 7;
    const int bloc = bq * 4 + bsub;
    const int k0   = kc * 128;
    const int grpoff = (bid >> 4) * 32;

    // one-time: load this CTA's U slice
    for (int i = tid; i < 4096; i += 512) {
        int k = i >> 3, jj = i & 7;
        U_s[i] = g_Upk[k * NSZ + cg * 8 + jj];
    }
    if (tid < 128) c_s[tid] = 0.f;
    __syncthreads();

    // per-warp staging geometry: warp (kc,bq) owns rows bq*4..+4, cols k0..k0+128
    const int srow = bq * 4 + (lane >> 3);
    const int scq  = lane & 7;

    for (int t = 0; t < TSZ; t++) {
        // -- prefetch gate pre-activations (independent of recurrence state) --
        float xi = 0.f, xf = 0.f, xg = 0.f, xc = 0.f;
        if (tid < 128) {
            int b = tid >> 3, jj = tid & 7;
            int bg = bh * 16 + b;
            size_t gbase = ((size_t)t * BSZ + bg) * (size_t)NCAT + (cg * 8 + jj);
            xi = __ldg(&g_G[gbase]);
            xf = __ldg(&g_G[gbase + NSZ]);
            xg = __ldg(&g_G[gbase + 2 * NSZ]);
            xc = __ldg(&g_G[gbase + 3 * NSZ]);
        }

        // -- per-warp staging of h (no CTA-wide sync needed) --
        {
            float* dst = &h_s[srow * HSTRIDE + k0];
            if (t == 0) {
#pragma unroll
                for (int i = 0; i < 4; i++)
                    *(float4*)&dst[(scq + 8 * i) * 4] = make_float4(0.f, 0.f, 0.f, 0.f);
            } else {
                const float* hp = &g_hs[((size_t)(t - 1) * BSZ + bh * 16 + srow) * NSZ + k0];
#pragma unroll
                for (int i = 0; i < 4; i++)
                    *(float4*)&dst[(scq + 8 * i) * 4] = *(const float4*)&hp[(scq + 8 * i) * 4];
            }
            __syncwarp();
        }

        // -- partial h @ U over this warp's 128-k chunk (f32x2: 2 MAC/instr) --
        unsigned long long a01 = 0ull, a23 = 0ull;   // (i,f) and (g,c)
        const float* hrow = &h_s[bloc * HSTRIDE + k0];
        const ulonglong2* up = (const ulonglong2*)U_s + ((size_t)k0 * 8 + j);
#pragma unroll 8
        for (int kk = 0; kk < 128; kk += 4) {
            float4 hv = *(const float4*)&hrow[kk];
            ulonglong2 u0 = up[(kk + 0) * 8];
            ulonglong2 u1 = up[(kk + 1) * 8];
            ulonglong2 u2 = up[(kk + 2) * 8];
            ulonglong2 u3 = up[(kk + 3) * 8];
            unsigned long long h2;
            PACK2SAME(h2, hv.x); FFMA2(a01, h2, u0.x); FFMA2(a23, h2, u0.y);
            PACK2SAME(h2, hv.y); FFMA2(a01, h2, u1.x); FFMA2(a23, h2, u1.y);
            PACK2SAME(h2, hv.z); FFMA2(a01, h2, u2.x); FFMA2(a23, h2, u2.y);
            PACK2SAME(h2, hv.w); FFMA2(a01, h2, u3.x); FFMA2(a23, h2, u3.y);
        }
        {
            uint32_t r0, r1, r2, r3;
            UNPACK2(r0, r1, a01);
            UNPACK2(r2, r3, a23);
            part[kc * 128 + bloc * 8 + j] =
                make_float4(__uint_as_float(r0), __uint_as_float(r1),
                            __uint_as_float(r2), __uint_as_float(r3));
        }
        __syncthreads();

        // -- reduce split-k, gate math, c update, emit h_t --
        if (tid < 128) {
            float4 s  = part[tid];
            float4 p1 = part[128 + tid];
            float4 p2 = part[256 + tid];
            float4 p3 = part[384 + tid];
            s.x += p1.x + p2.x + p3.x;
            s.y += p1.y + p2.y + p3.y;
            s.z += p1.z + p2.z + p3.z;
            s.w += p1.w + p2.w + p3.w;

            int b = tid >> 3, jj = tid & 7;
            int bg = bh * 16 + b;
            int n  = cg * 8 + jj;

            float ig = 1.f / (1.f + __expf(-(s.x + xi)));
            float fg = 1.f / (1.f + __expf(-(s.y + xf)));
            float gg = 1.f / (1.f + __expf(-(s.z + xg)));
            float ct = tanhf(s.w + xc);

            float c = fg * c_s[tid] + ig * ct;
            c_s[tid] = c;
            float h = gg * tanhf(c);
            g_hs[((size_t)t * BSZ + bg) * NSZ + n] = h;
        }
        __syncthreads();

        // -- two-level grid barrier (monotonic counters, tid0 only) --
        if (tid == 0) {
            __threadfence();
            int v = atomicAdd(&g_cnt[grpoff], 1);
            if (v == t * 16 + 15) {
                __threadfence();
                int r = atomicAdd(&g_root2, 1);
                if (r == t * 8 + 7) {
                    __threadfence();
                    *((volatile int*)&g_flagv) = t + 1;
                }
            }
            while (*((volatile int*)&g_flagv) < t + 1) {}
            __threadfence();
        }
        __syncthreads();
    }
}

// ---------------- launcher ---------------------------------------------------
extern "C" void kernel_launch(void* const* d_in, const int* in_sizes, int n_in,
                              void* d_out, int out_size)
{
    (void)in_sizes; (void)n_in; (void)out_size;
    const float* x   = (const float*)d_in[0];
    const float* W_i = (const float*)d_in[1];
    const float* U_i = (const float*)d_in[2];
    const float* W_f = (const float*)d_in[3];
    const float* U_f = (const float*)d_in[4];
    const float* W_g = (const float*)d_in[5];
    const float* U_g = (const float*)d_in[6];
    const float* W_c = (const float*)d_in[7];
    const float* U_c = (const float*)d_in[8];
    const float* W_o = (const float*)d_in[9];
    const float* b_i = (const float*)d_in[10];
    const float* b_f = (const float*)d_in[11];
    const float* b_g = (const float*)d_in[12];
    const float* b_c = (const float*)d_in[13];
    const float* b_o = (const float*)d_in[14];
    float* out = (float*)d_out;

    cudaFuncSetAttribute(lstm_recur_kernel,
                         cudaFuncAttributeMaxDynamicSharedMemorySize, SMEM_FLOATS * 4);
    cudaFuncSetAttribute(gemm_mma_kernel,
                         cudaFuncAttributeMaxDynamicSharedMemorySize, GSM_TOTAL);

    // launches 0..4: prep (merged so launch #5 is the gates GEMM for ncu -s 5)
    pack_u_kernel<<<(DSZ * NSZ) / 256, 256>>>(U_i, U_f, U_g, U_c);                 // 0
    cvt_x_kernel<<<(int)(((size_t)MROWS * DSZ / 4) / 256), 256>>>(x);              // 1
    {
        dim3 g(16, 16, 4), b(32, 8);
        wtrans4_kernel<<<g, b>>>(W_i, W_f, W_g, W_c);                              // 2
    }
    biascat_kernel<<<2, 256>>>(b_i, b_f, b_g, b_c);                                // 3
    reset_sync_kernel<<<1, 256>>>();                                               // 4

    // 5: input projections for all 4 gates (profiled launch)
    gemm_mma_kernel<<<dim3(NCAT / 128, MROWS / 128), 256, GSM_TOTAL>>>(nullptr, nullptr, 0);

    // 6: persistent recurrence
    lstm_recur_kernel<<<128, 512, SMEM_FLOATS * 4>>>();

    // 7..9: output projection
    cvt_hs_kernel<<<(int)(((size_t)MROWS * NSZ / 4) / 256), 256>>>();              // 7
    {
        dim3 g(16, 16), b(32, 8);
        wtrans_kernel<<<g, b>>>(W_o, 0);                                           // 8
    }
    gemm_mma_kernel<<<dim3(NSZ / 128, MROWS / 128), 256, GSM_TOTAL>>>(b_o, out, 1); // 9
}